// round 11
// baseline (speedup 1.0000x reference)
#include <cuda_runtime.h>
#include <cuda_bf16.h>

// targets: (64, 512, 1024) int32; live region = [:64, :64, :] (16 MiB)
// pc:      (64, 1, 64, 128) float32 (2 MiB)
// loss = -(1/N) * [ sum log(1-pc) + sum_corner cond(i,j)*(log pc - log(1-pc)) ]
// cond(i,j) = (0 < count_ij < 64); count_ij over targets[8i:8i+8, 8j:8j+8, :].
//
// Block bid covers batch r=bid>>3, patch column j=bid&7, rows c=8j+wid:
// exactly one patch slice. Sample = first 128 ints of each of the block's own
// 8 rows (1 int4 per thread, no redundant addresses). If block-sample >= 64,
// block partial >= 64 is proven -> sentinel (cond=0 regardless of others,
// for ANY input). Else exact full-row fallback. Product-log for the BCE term.

#define N_PC    524288
#define GRID    512      // power of two: monotonic done-counter wraps cleanly
#define THREADS 256

__device__ int          g_blkcnt[GRID];   // plain stores, overwritten each replay
__device__ float        g_partial[GRID];  // plain stores, overwritten each replay
__device__ unsigned int g_done;           // monotonic arrival counter (zero-init at load)

__global__ __launch_bounds__(THREADS) void fused_kernel(
    const float4* __restrict__ pc4,
    const int4*   __restrict__ tg4,
    const float*  __restrict__ pc,
    float*        __restrict__ out)
{
    const int tid  = threadIdx.x;
    const int bid  = blockIdx.x;
    const int wid  = tid >> 5;
    const int lane = tid & 31;

    // ---- warp's targets row: r = bid>>3 (batch), c = 8*(bid&7)+wid
    const int4* base = tg4 + (size_t)(bid >> 3) * 131072u
                           + (size_t)(8 * (bid & 7) + wid) * 256u;

    // ---- both loads issued up front (2 LDG per thread total on fast path)
    float4 v = pc4[bid * THREADS + tid];
    int4   q = base[lane];                 // sample: first 128 ints of own row

    int scnt = (q.x == 2) + (q.y == 2) + (q.z == 2) + (q.w == 2);
    scnt = __reduce_add_sync(0xffffffffu, scnt);   // warp sample count

    __shared__ int   sc[8];
    __shared__ float sp[8];
    if (lane == 0) sc[wid] = scnt;

    // ---- BCE partial while the sample reduce settles:
    float prod = (1.0f - v.x) * (1.0f - v.y) * (1.0f - v.z) * (1.0f - v.w);
    float s = __logf(prod);
    #pragma unroll
    for (int o = 16; o > 0; o >>= 1)
        s += __shfl_down_sync(0xffffffffu, s, o);

    __syncthreads();
    int S = 0;
    #pragma unroll
    for (int k = 0; k < 8; k++) S += sc[k];        // block-uniform sample count

    int cnt;
    if (S >= 64) {
        cnt = 1 << 17;   // block partial >= 64 proven; sentinel (8 warps -> 1<<20)
    } else {
        // exact fallback: full row (1024 ints = 256 int4)
        int t = 0;
        #pragma unroll
        for (int k = 0; k < 8; k++) {
            int4 w = base[lane + k * 32];
            t += (w.x == 2) + (w.y == 2) + (w.z == 2) + (w.w == 2);
        }
        cnt = __reduce_add_sync(0xffffffffu, t);
    }

    if (lane == 0) { sp[wid] = s; sc[wid] = cnt; }
    __syncthreads();

    // ---- tid0: combine, release-fence, arrive
    __shared__ unsigned int s_last;
    if (tid == 0) {
        float bs = 0.0f; int bc = 0;
        #pragma unroll
        for (int k = 0; k < 8; k++) { bs += sp[k]; bc += sc[k]; }
        g_partial[bid] = bs;
        g_blkcnt[bid]  = bc;               // one patch (i=bid>>6, j=bid&7) per block
        __threadfence();                   // release
        unsigned int old = atomicAdd(&g_done, 1u);
        s_last = ((old & (GRID - 1u)) == GRID - 1u) ? 1u : 0u;
    }
    __syncthreads();
    if (!s_last) return;

    if (tid == 0) __threadfence();         // acquire
    __syncthreads();

    // ================= last block: aggregate =================
    __shared__ float  s_cond[64];
    __shared__ double s_red[8];

    // patch (i,j) -> blocks b = 8*(8i+rr) + j, rr = 0..7
    if (tid < 64) {
        const int i = tid >> 3, j = tid & 7;
        int pcnt = 0;
        #pragma unroll
        for (int rr = 0; rr < 8; rr++)
            pcnt += g_blkcnt[8 * (8 * i + rr) + j];
        s_cond[tid] = (pcnt > 0 && pcnt < 64) ? 1.0f : 0.0f;
    }
    __syncthreads();

    // base sum from 512 partials (double), 2 per thread
    double acc = (double)g_partial[tid] + (double)g_partial[tid + 256];

    // corner correction: 64 (i,j) x 64 batches, L2-hot pc reloads
    {
        const int ij = tid & 63;
        const int i  = ij >> 3, j = ij & 7;
        if (s_cond[ij] != 0.0f) {
            const int b0 = (tid >> 6) * 16;
            float csum = 0.0f;
            #pragma unroll 4
            for (int b = b0; b < b0 + 16; b++) {
                float p = pc[(size_t)b * 8192u + i * 128 + j];
                csum += __logf(p / (1.0f - p));
            }
            acc += (double)csum;
        }
    }

    #pragma unroll
    for (int o = 16; o > 0; o >>= 1)
        acc += __shfl_down_sync(0xffffffffu, acc, o);
    if (lane == 0) s_red[wid] = acc;
    __syncthreads();
    if (tid == 0) {
        double total = 0.0;
        #pragma unroll
        for (int k = 0; k < 8; k++) total += s_red[k];
        out[0] = (float)(-total / (double)N_PC);
    }
}

extern "C" void kernel_launch(void* const* d_in, const int* in_sizes, int n_in,
                              void* d_out, int out_size) {
    const float* pc;
    const int*   tg;
    if (in_sizes[0] == N_PC) {
        pc = (const float*)d_in[0];
        tg = (const int*)  d_in[1];
    } else {
        pc = (const float*)d_in[1];
        tg = (const int*)  d_in[0];
    }
    fused_kernel<<<GRID, THREADS>>>((const float4*)pc, (const int4*)tg,
                                    pc, (float*)d_out);
}